// round 4
// baseline (speedup 1.0000x reference)
#include <cuda_runtime.h>
#include <cuda_bf16.h>
#include <cstdint>

// ---------------------------------------------------------------------------
// GraphSAGE, mma.sync bf16 hi/lo split (3-product), double-buffered pipeline.
//   CTA tile: M=64 x N=256 (self|neigh), K=256 chunked by 64, 512 threads.
//   MODE 0: F0 = relu([emb[nodeids]@Ws0' | mean3(emb[neigh1])@Wn0'])  (split store)
//   MODE 1: F1 = relu([emb[neigh1] @Ws0' | mean5(emb[neigh2])@Wn0'])  (fp32 store)
//   MODE 2: h  = relu([F0@Ws1' | mean3(F1)@Wn1']); h/=||h||; out = h@fc' + b
// ---------------------------------------------------------------------------

#define B_ROOT 16384
#define R1     49152
#define RS1    72            // tile row stride (bf16 elems)
#define RSH    264           // mode-2 h row stride

// stage-relative byte offsets
#define O_ASH  0             // self A hi  [64][72]
#define O_ASL  9216
#define O_ANH  18432
#define O_ANL  27648
#define O_WH   36864         // W hi [256][72]
#define O_WL   73728
#define STAGE_BYTES 110592
#define SMEM_BYTES  221184
// mode-2 aliases (used after stage-1 pipeline drains)
#define O_HH   0             // h hi [64][264]
#define O_HL   33792
#define O_SS   67584         // float ss[64]
#define O_FC   110592        // fc tiles, + s*36864 (hi at +0, lo at +18432)
#define FCSTG  36864

// ---------------- scratch ----------------------------------------------------
__device__ __nv_bfloat16 g_whi[5 * 32768];
__device__ __nv_bfloat16 g_wlo[5 * 32768];
__device__ __nv_bfloat16 g_F0h[B_ROOT * 256];
__device__ __nv_bfloat16 g_F0l[B_ROOT * 256];
__device__ float         g_F1 [R1 * 256];

// ---------------- helpers ----------------------------------------------------
__device__ __forceinline__ uint32_t smem_u32(const void* p) {
    uint32_t a;
    asm("{ .reg .u64 t; cvta.to.shared.u64 t, %1; cvt.u32.u64 %0, t; }"
        : "=r"(a) : "l"(p));
    return a;
}
__device__ __forceinline__ void split2(float a, float b, uint32_t& h, uint32_t& l) {
    __nv_bfloat16 ah = __float2bfloat16_rn(a), bh = __float2bfloat16_rn(b);
    __nv_bfloat16 al = __float2bfloat16_rn(a - __bfloat162float(ah));
    __nv_bfloat16 bl = __float2bfloat16_rn(b - __bfloat162float(bh));
    __nv_bfloat162 ph = __halves2bfloat162(ah, bh);
    __nv_bfloat162 pl = __halves2bfloat162(al, bl);
    h = *reinterpret_cast<uint32_t*>(&ph);
    l = *reinterpret_cast<uint32_t*>(&pl);
}
__device__ __forceinline__ void split8(const float* v, uint4& h4, uint4& l4) {
    uint32_t h[4], l[4];
#pragma unroll
    for (int i = 0; i < 4; ++i) split2(v[2 * i], v[2 * i + 1], h[i], l[i]);
    h4 = make_uint4(h[0], h[1], h[2], h[3]);
    l4 = make_uint4(l[0], l[1], l[2], l[3]);
}
__device__ __forceinline__ void mma16816(float* d, const uint32_t* a,
                                         uint32_t b0, uint32_t b1) {
    asm volatile(
        "mma.sync.aligned.m16n8k16.row.col.f32.bf16.bf16.f32 "
        "{%0,%1,%2,%3}, {%4,%5,%6,%7}, {%8,%9}, {%0,%1,%2,%3};"
        : "+f"(d[0]), "+f"(d[1]), "+f"(d[2]), "+f"(d[3])
        : "r"(a[0]), "r"(a[1]), "r"(a[2]), "r"(a[3]), "r"(b0), "r"(b1));
}
__device__ __forceinline__ void ldmx4(uint32_t* r, uint32_t a) {
    asm volatile("ldmatrix.sync.aligned.m8n8.x4.shared.b16 {%0,%1,%2,%3}, [%4];"
                 : "=r"(r[0]), "=r"(r[1]), "=r"(r[2]), "=r"(r[3]) : "r"(a));
}
__device__ __forceinline__ void cp16(uint32_t dst, const void* src) {
    asm volatile("cp.async.cg.shared.global [%0], [%1], 16;" :: "r"(dst), "l"(src));
}
#define CP_COMMIT() asm volatile("cp.async.commit_group;" ::: "memory")
#define CP_WAIT0()  asm volatile("cp.async.wait_group 0;"  ::: "memory")

// ---------------- weight pre-split --------------------------------------------
__global__ void conv_w(const float* __restrict__ a, const float* __restrict__ b,
                       const float* __restrict__ c, const float* __restrict__ d,
                       const float* __restrict__ e,
                       __nv_bfloat16* __restrict__ hi, __nv_bfloat16* __restrict__ lo) {
    int t = blockIdx.x * blockDim.x + threadIdx.x;
    const float* src[5] = {a, b, c, d, e};
    float x = src[t >> 15][t & 32767];
    __nv_bfloat16 h = __float2bfloat16_rn(x);
    hi[t] = h;
    lo[t] = __float2bfloat16_rn(x - __bfloat162float(h));
}

// ---------------- fused agg kernel --------------------------------------------
template <int MODE>
__global__ void __launch_bounds__(512, 1)
agg_kernel(const float* __restrict__ srcS_f,
           const __nv_bfloat16* __restrict__ srcS_h, const __nv_bfloat16* __restrict__ srcS_l,
           const float* __restrict__ srcN,
           const int* __restrict__ idxS, const int* __restrict__ idxN,
           const __nv_bfloat16* __restrict__ wS_hi, const __nv_bfloat16* __restrict__ wS_lo,
           const __nv_bfloat16* __restrict__ wN_hi, const __nv_bfloat16* __restrict__ wN_lo,
           const float* __restrict__ bS, const float* __restrict__ bN,
           __nv_bfloat16* __restrict__ outFh, __nv_bfloat16* __restrict__ outFl,
           float* __restrict__ outF,
           const __nv_bfloat16* __restrict__ fc_hi, const __nv_bfloat16* __restrict__ fc_lo,
           const float* __restrict__ fcb, float* __restrict__ out2)
{
    constexpr int KF = (MODE == 1) ? 5 : 3;
    extern __shared__ char smem[];
    const uint32_t sb = smem_u32(smem);

    const int tid = threadIdx.x, lane = tid & 31, wid = tid >> 5;
    const int wm = wid >> 3, wn = wid & 7;           // 2 x 8 warp grid, 32x32 tiles
    const int lr = lane >> 2, lc = (lane & 3) * 2;
    const int g  = lane >> 3, lm = lane & 7;
    const int aro = ((g & 1) << 3) + lm, aco = (g >> 1) << 3;
    const int bro = ((g >> 1) << 3) + lm, bco = (g & 1) << 3;
    const int m0 = blockIdx.x * 64;

    // loader roles: threads 0..255 self, 256..511 neigh
    const bool isSelf = tid < 256;
    const int lt = tid & 255;
    const int lrow = lt >> 2, lcq = (lt & 3) * 16;

    int rowS = 0;
    int rowN[KF];
    if (MODE != 2) {
        if (isSelf) rowS = idxS[m0 + lrow];
        else {
#pragma unroll
            for (int j = 0; j < KF; ++j)
                rowN[j] = idxN[(size_t)(m0 + lrow) * KF + j];
        }
    } else if (!isSelf) {
#pragma unroll
        for (int j = 0; j < KF; ++j) rowN[j] = (m0 + lrow) * 3 + j;
    }

    float v[16];

    auto PREFETCH = [&](int ch) {
        const int kb = ch * 64;
        if (isSelf) {
            if (MODE != 2) {
                const float4* p = (const float4*)(srcS_f + (size_t)rowS * 256 + kb + lcq);
#pragma unroll
                for (int q = 0; q < 4; ++q) {
                    float4 f = __ldg(p + q);
                    v[q * 4 + 0] = f.x; v[q * 4 + 1] = f.y;
                    v[q * 4 + 2] = f.z; v[q * 4 + 3] = f.w;
                }
            }
        } else {
#pragma unroll
            for (int i = 0; i < 16; ++i) v[i] = 0.f;
#pragma unroll
            for (int j = 0; j < KF; ++j) {
                const float4* p = (const float4*)(srcN + (size_t)rowN[j] * 256 + kb + lcq);
#pragma unroll
                for (int q = 0; q < 4; ++q) {
                    float4 f = __ldg(p + q);
                    v[q * 4 + 0] += f.x; v[q * 4 + 1] += f.y;
                    v[q * 4 + 2] += f.z; v[q * 4 + 3] += f.w;
                }
            }
        }
    };

    auto STORE_A = [&](int buf) {
        if (MODE == 2 && isSelf) return;
        float w[16];
        const float s = isSelf ? 1.0f : (1.0f / (float)KF);
#pragma unroll
        for (int i = 0; i < 16; ++i) w[i] = v[i] * s;
        uint4 h0, l0, h1, l1;
        split8(w, h0, l0);
        split8(w + 8, h1, l1);
        char* base = smem + buf * STAGE_BYTES + (isSelf ? O_ASH : O_ANH)
                   + (size_t)(lrow * RS1 + lcq) * 2;
        *(uint4*)(base)               = h0;
        *(uint4*)(base + 16)          = h1;
        *(uint4*)(base + 9216)        = l0;
        *(uint4*)(base + 9216 + 16)   = l1;
    };

    auto ISSUE_W = [&](int ch, int buf) {
        const int kb = ch * 64;
#pragma unroll
        for (int i = 0; i < 8; ++i) {
            int o = tid + i * 512;
            int plane = o >> 11, idx = o & 2047;
            int row = idx >> 3, col = (idx & 7) * 8;
            const __nv_bfloat16* src =
                plane ? ((row < 128) ? wS_lo + (size_t)row * 256
                                     : wN_lo + (size_t)(row - 128) * 256)
                      : ((row < 128) ? wS_hi + (size_t)row * 256
                                     : wN_hi + (size_t)(row - 128) * 256);
            uint32_t dst = sb + buf * STAGE_BYTES + (plane ? O_WL : O_WH)
                         + (uint32_t)(row * RS1 + col) * 2;
            cp16(dst, src + kb + col);
        }
    };

    auto ISSUE_SELF = [&](int ch, int buf) {   // MODE 2 only, threads < 256
        if (!isSelf) return;
        const int kb = ch * 64;
#pragma unroll
        for (int i = 0; i < 4; ++i) {
            int o = tid + i * 256;
            int plane = o >> 9, idx = o & 511;
            int row = idx >> 3, col = (idx & 7) * 8;
            const __nv_bfloat16* src = (plane ? srcS_l : srcS_h)
                                     + (size_t)(m0 + row) * 256 + kb + col;
            uint32_t dst = sb + buf * STAGE_BYTES + (plane ? O_ASL : O_ASH)
                         + (uint32_t)(row * RS1 + col) * 2;
            cp16(dst, src);
        }
    };

    float d[2][4][4];
#pragma unroll
    for (int i = 0; i < 2; ++i)
#pragma unroll
        for (int j = 0; j < 4; ++j)
#pragma unroll
            for (int k = 0; k < 4; ++k) d[i][j][k] = 0.f;

    auto MMA1 = [&](int buf) {
        const uint32_t stg = sb + buf * STAGE_BYTES;
        const uint32_t aBH = stg + (wn < 4 ? O_ASH : O_ANH);
        const uint32_t aBL = aBH + 9216;
        const uint32_t bBH = stg + O_WH;
        const uint32_t bBL = stg + O_WL;
#pragma unroll
        for (int ks = 0; ks < 4; ++ks) {
            uint32_t ah[2][4], al[2][4];
#pragma unroll
            for (int mi = 0; mi < 2; ++mi) {
                uint32_t ad = (uint32_t)((wm * 32 + mi * 16 + aro) * RS1
                                         + ks * 16 + aco) * 2;
                ldmx4(ah[mi], aBH + ad);
                ldmx4(al[mi], aBL + ad);
            }
            uint32_t bh[4][2], bl[4][2];
#pragma unroll
            for (int nip = 0; nip < 2; ++nip) {
                uint32_t bd = (uint32_t)((wn * 32 + nip * 16 + bro) * RS1
                                         + ks * 16 + bco) * 2;
                uint32_t t4[4];
                ldmx4(t4, bBH + bd);
                bh[2 * nip][0] = t4[0]; bh[2 * nip][1] = t4[1];
                bh[2 * nip + 1][0] = t4[2]; bh[2 * nip + 1][1] = t4[3];
                ldmx4(t4, bBL + bd);
                bl[2 * nip][0] = t4[0]; bl[2 * nip][1] = t4[1];
                bl[2 * nip + 1][0] = t4[2]; bl[2 * nip + 1][1] = t4[3];
            }
#pragma unroll
            for (int ni = 0; ni < 4; ++ni)
#pragma unroll
                for (int mi = 0; mi < 2; ++mi) {
                    mma16816(d[mi][ni], ah[mi], bh[ni][0], bh[ni][1]);
                    mma16816(d[mi][ni], ah[mi], bl[ni][0], bl[ni][1]);
                    mma16816(d[mi][ni], al[mi], bh[ni][0], bh[ni][1]);
                }
        }
    };

    // ================= stage-1 pipeline =======================================
    PREFETCH(0);
    ISSUE_W(0, 0);
    if (MODE == 2) ISSUE_SELF(0, 0);
    CP_COMMIT();
    STORE_A(0);
    CP_WAIT0();
    __syncthreads();

#pragma unroll
    for (int ch = 0; ch < 4; ++ch) {
        const int cb = ch & 1, nb = cb ^ 1;
        if (ch < 3) {
            PREFETCH(ch + 1);
            ISSUE_W(ch + 1, nb);
            if (MODE == 2) ISSUE_SELF(ch + 1, nb);
            CP_COMMIT();
        }
        MMA1(cb);
        if (ch < 3) STORE_A(nb);
        CP_WAIT0();
        __syncthreads();
    }

    // ================= epilogues ==============================================
    if (MODE != 2) {
#pragma unroll
        for (int mi = 0; mi < 2; ++mi) {
            const int row = m0 + wm * 32 + mi * 16 + lr;
#pragma unroll
            for (int ni = 0; ni < 4; ++ni) {
                const int col = wn * 32 + ni * 8 + lc;
                const float b0 = (col < 128) ? bS[col] : bN[col - 128];
                const float b1 = (col + 1 < 128) ? bS[col + 1] : bN[col - 127];
                float v00 = fmaxf(d[mi][ni][0] + b0, 0.f);
                float v01 = fmaxf(d[mi][ni][1] + b1, 0.f);
                float v10 = fmaxf(d[mi][ni][2] + b0, 0.f);
                float v11 = fmaxf(d[mi][ni][3] + b1, 0.f);
                if (MODE == 0) {
                    uint32_t h, l;
                    split2(v00, v01, h, l);
                    *(uint32_t*)(outFh + (size_t)row * 256 + col) = h;
                    *(uint32_t*)(outFl + (size_t)row * 256 + col) = l;
                    split2(v10, v11, h, l);
                    *(uint32_t*)(outFh + (size_t)(row + 8) * 256 + col) = h;
                    *(uint32_t*)(outFl + (size_t)(row + 8) * 256 + col) = l;
                } else {
                    *(float2*)(outF + (size_t)row * 256 + col) = make_float2(v00, v01);
                    *(float2*)(outF + (size_t)(row + 8) * 256 + col) = make_float2(v10, v11);
                }
            }
        }
        return;
    }

    // ---------------- MODE 2: bias+relu, L2 norm, h->smem, FC -----------------
    float* ss = (float*)(smem + O_SS);
    if (tid < 64) ss[tid] = 0.f;

    // prefetch fc chunk 0 while epilogue math runs
    auto ISSUE_FC = [&](int ch, int buf) {
        const int kb = ch * 64;
#pragma unroll
        for (int i = 0; i < 4; ++i) {
            int o = tid + i * 512;
            int plane = o >> 10, idx = o & 1023;
            int row = idx >> 3, col = (idx & 7) * 8;
            const __nv_bfloat16* src = (plane ? fc_lo : fc_hi)
                                     + (size_t)row * 256 + kb + col;
            uint32_t dst = sb + O_FC + buf * FCSTG + (plane ? 18432 : 0)
                         + (uint32_t)(row * RS1 + col) * 2;
            cp16(dst, src);
        }
    };
    ISSUE_FC(0, 0);
    CP_COMMIT();
    __syncthreads();

    // bias + relu + row sum-of-squares
#pragma unroll
    for (int mi = 0; mi < 2; ++mi) {
        const int r0 = wm * 32 + mi * 16 + lr;
        float s0 = 0.f, s1 = 0.f;
#pragma unroll
        for (int ni = 0; ni < 4; ++ni) {
            const int col = wn * 32 + ni * 8 + lc;
            const float b0 = (col < 128) ? bS[col] : bN[col - 128];
            const float b1 = (col + 1 < 128) ? bS[col + 1] : bN[col - 127];
            d[mi][ni][0] = fmaxf(d[mi][ni][0] + b0, 0.f);
            d[mi][ni][1] = fmaxf(d[mi][ni][1] + b1, 0.f);
            d[mi][ni][2] = fmaxf(d[mi][ni][2] + b0, 0.f);
            d[mi][ni][3] = fmaxf(d[mi][ni][3] + b1, 0.f);
            s0 += d[mi][ni][0] * d[mi][ni][0] + d[mi][ni][1] * d[mi][ni][1];
            s1 += d[mi][ni][2] * d[mi][ni][2] + d[mi][ni][3] * d[mi][ni][3];
        }
        s0 += __shfl_xor_sync(0xffffffffu, s0, 1);
        s0 += __shfl_xor_sync(0xffffffffu, s0, 2);
        s1 += __shfl_xor_sync(0xffffffffu, s1, 1);
        s1 += __shfl_xor_sync(0xffffffffu, s1, 2);
        if ((lane & 3) == 0) {
            atomicAdd(&ss[r0], s0);
            atomicAdd(&ss[r0 + 8], s1);
        }
    }
    __syncthreads();

    // scale + split -> h tiles
#pragma unroll
    for (int mi = 0; mi < 2; ++mi) {
        const int r0 = wm * 32 + mi * 16 + lr;
        const float sc0 = 1.0f / fmaxf(sqrtf(ss[r0]), 1e-12f);
        const float sc1 = 1.0f / fmaxf(sqrtf(ss[r0 + 8]), 1e-12f);
#pragma unroll
        for (int ni = 0; ni < 4; ++ni) {
            const int col = wn * 32 + ni * 8 + lc;
            uint32_t h, l;
            split2(d[mi][ni][0] * sc0, d[mi][ni][1] * sc0, h, l);
            *(uint32_t*)(smem + O_HH + (size_t)(r0 * RSH + col) * 2) = h;
            *(uint32_t*)(smem + O_HL + (size_t)(r0 * RSH + col) * 2) = l;
            split2(d[mi][ni][2] * sc1, d[mi][ni][3] * sc1, h, l);
            *(uint32_t*)(smem + O_HH + (size_t)((r0 + 8) * RSH + col) * 2) = h;
            *(uint32_t*)(smem + O_HL + (size_t)((r0 + 8) * RSH + col) * 2) = l;
        }
    }
    CP_WAIT0();
    __syncthreads();

    // ---- stage 2: out = h @ fc^T, M=64 N=128, fc double-buffered --------------
    const int wm2 = wid >> 2, wn2 = wid & 3;
    float e[4][4];
#pragma unroll
    for (int i = 0; i < 4; ++i)
#pragma unroll
        for (int k = 0; k < 4; ++k) e[i][k] = 0.f;

#pragma unroll
    for (int ch = 0; ch < 4; ++ch) {
        const int cb = ch & 1, nb = cb ^ 1;
        if (ch < 3) { ISSUE_FC(ch + 1, nb); CP_COMMIT(); }
        const int kb = ch * 64;
        const uint32_t fH = sb + O_FC + cb * FCSTG;
        const uint32_t fL = fH + 18432;
#pragma unroll
        for (int ks = 0; ks < 4; ++ks) {
            uint32_t ah[4], al2[4];
            uint32_t ad = (uint32_t)((wm2 * 16 + aro) * RSH + kb + ks * 16 + aco) * 2;
            ldmx4(ah,  sb + O_HH + ad);
            ldmx4(al2, sb + O_HL + ad);
            uint32_t bh[4][2], bl[4][2];
#pragma unroll
            for (int nip = 0; nip < 2; ++nip) {
                uint32_t bd = (uint32_t)((wn2 * 32 + nip * 16 + bro) * RS1
                                         + ks * 16 + bco) * 2;
                uint32_t t4[4];
                ldmx4(t4, fH + bd);
                bh[2 * nip][0] = t4[0]; bh[2 * nip][1] = t4[1];
                bh[2 * nip + 1][0] = t4[2]; bh[2 * nip + 1][1] = t4[3];
                ldmx4(t4, fL + bd);
                bl[2 * nip][0] = t4[0]; bl[2 * nip][1] = t4[1];
                bl[2 * nip + 1][0] = t4[2]; bl[2 * nip + 1][1] = t4[3];
            }
#pragma unroll
            for (int ni = 0; ni < 4; ++ni) {
                mma16816(e[ni], ah, bh[ni][0], bh[ni][1]);
                mma16816(e[ni], ah, bl[ni][0], bl[ni][1]);
                mma16816(e[ni], al2, bh[ni][0], bh[ni][1]);
            }
        }
        CP_WAIT0();
        __syncthreads();
    }

    // final: + fc_b -> out2
#pragma unroll
    for (int ni = 0; ni < 4; ++ni) {
        const int col = wn2 * 32 + ni * 8 + lc;
        const int row = m0 + wm2 * 16 + lr;
        *(float2*)(out2 + (size_t)row * 128 + col) =
            make_float2(e[ni][0] + fcb[col], e[ni][1] + fcb[col + 1]);
        *(float2*)(out2 + (size_t)(row + 8) * 128 + col) =
            make_float2(e[ni][2] + fcb[col], e[ni][3] + fcb[col + 1]);
    }
}

// ---------------------------------------------------------------------------
extern "C" void kernel_launch(void* const* d_in, const int* in_sizes, int n_in,
                              void* d_out, int out_size)
{
    const float* emb      = (const float*)d_in[0];
    const float* w_self0  = (const float*)d_in[1];
    const float* b_self0  = (const float*)d_in[2];
    const float* w_neigh0 = (const float*)d_in[3];
    const float* b_neigh0 = (const float*)d_in[4];
    const float* w_self1  = (const float*)d_in[5];
    const float* b_self1  = (const float*)d_in[6];
    const float* w_neigh1 = (const float*)d_in[7];
    const float* b_neigh1 = (const float*)d_in[8];
    const float* fc_w     = (const float*)d_in[9];
    const float* fc_b     = (const float*)d_in[10];
    const int*   nodeids  = (const int*)d_in[11];
    const int*   neigh1   = (const int*)d_in[12];
    const int*   neigh2   = (const int*)d_in[13];
    float*       out      = (float*)d_out;

    __nv_bfloat16 *WHI, *WLO, *F0h, *F0l;
    float *F1;
    cudaGetSymbolAddress((void**)&WHI, g_whi);
    cudaGetSymbolAddress((void**)&WLO, g_wlo);
    cudaGetSymbolAddress((void**)&F0h, g_F0h);
    cudaGetSymbolAddress((void**)&F0l, g_F0l);
    cudaGetSymbolAddress((void**)&F1,  g_F1);

    cudaFuncSetAttribute(agg_kernel<0>, cudaFuncAttributeMaxDynamicSharedMemorySize, SMEM_BYTES);
    cudaFuncSetAttribute(agg_kernel<1>, cudaFuncAttributeMaxDynamicSharedMemorySize, SMEM_BYTES);
    cudaFuncSetAttribute(agg_kernel<2>, cudaFuncAttributeMaxDynamicSharedMemorySize, SMEM_BYTES);

    conv_w<<<640, 256>>>(w_self0, w_neigh0, w_self1, w_neigh1, fc_w, WHI, WLO);

    // layer0 F0 (split store): self = emb[nodeids], neigh = mean3 emb[neigh1]
    agg_kernel<0><<<B_ROOT / 64, 512, SMEM_BYTES>>>(
        emb, nullptr, nullptr, emb, nodeids, neigh1,
        WHI, WLO, WHI + 32768, WLO + 32768,
        b_self0, b_neigh0, F0h, F0l, nullptr,
        nullptr, nullptr, nullptr, nullptr);

    // layer0 F1 (fp32 store): self = emb[neigh1], neigh = mean5 emb[neigh2]
    agg_kernel<1><<<R1 / 64, 512, SMEM_BYTES>>>(
        emb, nullptr, nullptr, emb, neigh1, neigh2,
        WHI, WLO, WHI + 32768, WLO + 32768,
        b_self0, b_neigh0, nullptr, nullptr, F1,
        nullptr, nullptr, nullptr, nullptr);

    // layer1 + norm + FC fused
    agg_kernel<2><<<B_ROOT / 64, 512, SMEM_BYTES>>>(
        nullptr, F0h, F0l, F1, nullptr, nullptr,
        WHI + 65536, WLO + 65536, WHI + 98304, WLO + 98304,
        b_self1, b_neigh1, nullptr, nullptr, nullptr,
        WHI + 131072, WLO + 131072, fc_b, out);
}